// round 1
// baseline (speedup 1.0000x reference)
#include <cuda_runtime.h>
#include <math.h>

// ---- problem constants ----
#define BATCH 4
#define SEQ   1024
#define NE    768
#define DI    1536          // d_inner
#define DS    64            // d_state
#define DTR   4             // dt_rank
#define XDBL  (DTR + 2*DS)  // 132
#define MROWS (BATCH*SEQ)   // 4096

// ---- scratch (device globals; no allocation allowed) ----
__device__ float g_xr   [(size_t)MROWS * 2 * DI]; // [4096, 3072]: [:,0:1536]=x_ssm_raw, [:,1536:]=res
__device__ float g_xc   [(size_t)MROWS * DI];     // conv+silu output
__device__ float g_xdbl [(size_t)MROWS * XDBL];   // x_dbl [4096,132]
__device__ float g_delta[(size_t)MROWS * DI];     // softplus delta
__device__ float g_u    [(size_t)MROWS * DI];     // (y + D*x) * silu(res)

// ============================================================
// Tiled fp32 GEMM:  C[M,N] = A[M,K] @ B[N,K]^T   (NT form)
// BM=BN=128, BK=16, 256 threads, 8x8 per thread.
// ============================================================
#define BM 128
#define BN 128
#define BK 16
#define TM 8
#define TN 8

__global__ __launch_bounds__(256) void gemm_nt(
    const float* __restrict__ A, const float* __restrict__ Bm,
    float* __restrict__ C, int M, int N, int K)
{
    __shared__ float As[BK][BM + 4];
    __shared__ float Bs[BK][BN + 4];

    const int tid  = threadIdx.x;
    const int tx   = tid & 15;       // 16 cols of threads
    const int ty   = tid >> 4;       // 16 rows of threads
    const int row0 = blockIdx.y * BM;
    const int col0 = blockIdx.x * BN;

    float acc[TM][TN];
    #pragma unroll
    for (int i = 0; i < TM; i++)
        #pragma unroll
        for (int j = 0; j < TN; j++) acc[i][j] = 0.f;

    for (int k0 = 0; k0 < K; k0 += BK) {
        // load A tile 128x16 (2 float4 per thread)
        #pragma unroll
        for (int i = 0; i < 2; i++) {
            int idx = tid + i * 256;        // 0..511 float4 slots
            int r = idx >> 2;               // 0..127
            int c = (idx & 3) << 2;         // 0,4,8,12
            int gr = row0 + r, gc = k0 + c;
            float4 v = make_float4(0.f, 0.f, 0.f, 0.f);
            if (gr < M) v = *(const float4*)(A + (size_t)gr * K + gc);
            As[c + 0][r] = v.x; As[c + 1][r] = v.y;
            As[c + 2][r] = v.z; As[c + 3][r] = v.w;
        }
        // load B tile 128x16
        #pragma unroll
        for (int i = 0; i < 2; i++) {
            int idx = tid + i * 256;
            int r = idx >> 2;
            int c = (idx & 3) << 2;
            int gn = col0 + r, gc = k0 + c;
            float4 v = make_float4(0.f, 0.f, 0.f, 0.f);
            if (gn < N) v = *(const float4*)(Bm + (size_t)gn * K + gc);
            Bs[c + 0][r] = v.x; Bs[c + 1][r] = v.y;
            Bs[c + 2][r] = v.z; Bs[c + 3][r] = v.w;
        }
        __syncthreads();

        #pragma unroll
        for (int k = 0; k < BK; k++) {
            float a[TM], b[TN];
            #pragma unroll
            for (int i = 0; i < TM; i++) a[i] = As[k][ty * TM + i];
            #pragma unroll
            for (int j = 0; j < TN; j++) b[j] = Bs[k][tx * TN + j];
            #pragma unroll
            for (int i = 0; i < TM; i++)
                #pragma unroll
                for (int j = 0; j < TN; j++)
                    acc[i][j] = fmaf(a[i], b[j], acc[i][j]);
        }
        __syncthreads();
    }

    #pragma unroll
    for (int i = 0; i < TM; i++) {
        int gr = row0 + ty * TM + i;
        if (gr >= M) continue;
        #pragma unroll
        for (int j = 0; j < TN; j++) {
            int gc = col0 + tx * TN + j;
            if (gc < N) C[(size_t)gr * N + gc] = acc[i][j];
        }
    }
}

// ============================================================
// Depthwise causal conv(4) + bias + SiLU
// ============================================================
__global__ __launch_bounds__(256) void conv_silu_kernel(
    const float* __restrict__ conv_w, const float* __restrict__ conv_b)
{
    int idx = blockIdx.x * blockDim.x + threadIdx.x;
    if (idx >= MROWS * DI) return;
    int d = idx % DI;
    int m = idx / DI;
    int t = m % SEQ;

    float acc = conv_b[d];
    #pragma unroll
    for (int k = 0; k < 4; k++) {
        int tt = t - 3 + k;
        if (tt >= 0)
            acc = fmaf(conv_w[d * 4 + k],
                       g_xr[(size_t)(m - 3 + k) * (2 * DI) + d], acc);
    }
    // silu(acc) = acc * sigmoid(acc)
    g_xc[idx] = acc / (1.f + __expf(-acc));
}

// ============================================================
// delta = softplus(x_dbl[:, :4] @ W_dt^T + b_dt)
// ============================================================
__global__ __launch_bounds__(256) void delta_kernel(
    const float* __restrict__ W_dt, const float* __restrict__ b_dt)
{
    int idx = blockIdx.x * blockDim.x + threadIdx.x;
    if (idx >= MROWS * DI) return;
    int d = idx % DI;
    int m = idx / DI;
    const float* xd = g_xdbl + (size_t)m * XDBL;
    float z = b_dt[d];
    #pragma unroll
    for (int r = 0; r < DTR; r++)
        z = fmaf(xd[r], W_dt[d * DTR + r], z);
    float sp = (z > 20.f) ? z : log1pf(__expf(z));
    g_delta[idx] = sp;
}

// ============================================================
// Selective scan: one warp per (b, d); each lane owns 2 states.
// Writes u = (y + D*x) * silu(res)
// ============================================================
__global__ __launch_bounds__(256) void scan_kernel(
    const float* __restrict__ A_log, const float* __restrict__ Dvec)
{
    const int warpId = threadIdx.x >> 5;
    const int lane   = threadIdx.x & 31;
    const int wg     = blockIdx.x * (blockDim.x >> 5) + warpId;
    if (wg >= BATCH * DI) return;
    const int b = wg / DI;
    const int d = wg % DI;
    const int n0 = 2 * lane;

    const float A0 = -__expf(A_log[d * DS + n0]);
    const float A1 = -__expf(A_log[d * DS + n0 + 1]);
    const float Dd = Dvec[d];

    const float* deltaP = g_delta + (size_t)b * SEQ * DI + d;
    const float* xP     = g_xc    + (size_t)b * SEQ * DI + d;
    const float* resP   = g_xr    + (size_t)b * SEQ * (2 * DI) + DI + d;
    const float* bcP    = g_xdbl  + (size_t)b * SEQ * XDBL;
    float*       uP     = g_u     + (size_t)b * SEQ * DI + d;

    float h0 = 0.f, h1 = 0.f;

    // prefetch t=0
    float  dt_n = deltaP[0];
    float  x_n  = xP[0];
    float  r_n  = resP[0];
    float2 B_n  = *(const float2*)(bcP + DTR + n0);
    float2 C_n  = *(const float2*)(bcP + DTR + DS + n0);

    for (int t = 0; t < SEQ; t++) {
        const float  dt = dt_n, xv = x_n, rv = r_n;
        const float2 Bv = B_n,  Cv = C_n;
        if (t + 1 < SEQ) {
            dt_n = deltaP[(size_t)(t + 1) * DI];
            x_n  = xP[(size_t)(t + 1) * DI];
            r_n  = resP[(size_t)(t + 1) * (2 * DI)];
            B_n  = *(const float2*)(bcP + (size_t)(t + 1) * XDBL + DTR + n0);
            C_n  = *(const float2*)(bcP + (size_t)(t + 1) * XDBL + DTR + DS + n0);
        }

        const float ab0 = __expf(dt * A0);
        const float ab1 = __expf(dt * A1);
        const float dx  = dt * xv;
        h0 = fmaf(ab0, h0, dx * Bv.x);
        h1 = fmaf(ab1, h1, dx * Bv.y);

        float p = fmaf(h0, Cv.x, h1 * Cv.y);
        #pragma unroll
        for (int o = 16; o; o >>= 1)
            p += __shfl_xor_sync(0xffffffffu, p, o);

        if (lane == 0) {
            const float y   = fmaf(Dd, xv, p);
            const float sig = 1.f / (1.f + __expf(-rv));
            uP[(size_t)t * DI] = y * (rv * sig);
        }
    }
}

// ============================================================
// launch
// ============================================================
extern "C" void kernel_launch(void* const* d_in, const int* in_sizes, int n_in,
                              void* d_out, int out_size)
{
    const float* x      = (const float*)d_in[0];
    const float* W_in   = (const float*)d_in[1];
    const float* conv_w = (const float*)d_in[2];
    const float* conv_b = (const float*)d_in[3];
    const float* W_x    = (const float*)d_in[4];
    const float* W_dt   = (const float*)d_in[5];
    const float* b_dt   = (const float*)d_in[6];
    const float* A_log  = (const float*)d_in[7];
    const float* Dvec   = (const float*)d_in[8];
    const float* W_out  = (const float*)d_in[9];
    float* out = (float*)d_out;

    void *p_xr, *p_xc, *p_xdbl, *p_u;
    cudaGetSymbolAddress(&p_xr,   g_xr);
    cudaGetSymbolAddress(&p_xc,   g_xc);
    cudaGetSymbolAddress(&p_xdbl, g_xdbl);
    cudaGetSymbolAddress(&p_u,    g_u);

    // 1) xr = x @ W_in^T : [4096, 3072], K=768
    {
        dim3 grid((2 * DI + BN - 1) / BN, (MROWS + BM - 1) / BM);
        gemm_nt<<<grid, 256>>>(x, W_in, (float*)p_xr, MROWS, 2 * DI, NE);
    }
    // 2) conv + silu
    {
        int n = MROWS * DI;
        conv_silu_kernel<<<(n + 255) / 256, 256>>>(conv_w, conv_b);
    }
    // 3) x_dbl = x_ssm @ W_x^T : [4096, 132], K=1536
    {
        dim3 grid((XDBL + BN - 1) / BN, (MROWS + BM - 1) / BM);
        gemm_nt<<<grid, 256>>>((const float*)p_xc, W_x, (float*)p_xdbl,
                               MROWS, XDBL, DI);
    }
    // 4) delta = softplus(x_dbl[:, :4] @ W_dt^T + b_dt)
    {
        int n = MROWS * DI;
        delta_kernel<<<(n + 255) / 256, 256>>>(W_dt, b_dt);
    }
    // 5) selective scan -> u
    {
        int nwarps = BATCH * DI;              // 6144
        int wpb = 8;                          // 256 threads
        scan_kernel<<<(nwarps + wpb - 1) / wpb, wpb * 32>>>(A_log, Dvec);
    }
    // 6) out = u @ W_out^T : [4096, 768], K=1536
    {
        dim3 grid((NE + BN - 1) / BN, (MROWS + BM - 1) / BM);
        gemm_nt<<<grid, 256>>>((const float*)p_u, W_out, out, MROWS, NE, DI);
    }
}

// round 4
// speedup vs baseline: 1.2084x; 1.2084x over previous
#include <cuda_runtime.h>
#include <cuda_bf16.h>
#include <cstdint>
#include <math.h>

// ---- problem constants ----
#define BATCH 4
#define SEQ   1024
#define NE    768
#define DI    1536          // d_inner
#define DS    64            // d_state
#define DTR   4             // dt_rank
#define XDBL  (DTR + 2*DS)  // 132
#define MROWS (BATCH*SEQ)   // 4096

// ---- fp32 scratch ----
__device__ float g_xr   [(size_t)MROWS * 2 * DI];
__device__ float g_xc   [(size_t)MROWS * DI];
__device__ float g_xdbl [(size_t)MROWS * XDBL];
__device__ float g_delta[(size_t)MROWS * DI];
__device__ float g_u    [(size_t)MROWS * DI];

// ---- bf16 hi/lo split operands ----
__device__ __nv_bfloat16 g_x_hi  [(size_t)MROWS * NE];
__device__ __nv_bfloat16 g_x_lo  [(size_t)MROWS * NE];
__device__ __nv_bfloat16 g_Win_hi[(size_t)2 * DI * NE];
__device__ __nv_bfloat16 g_Win_lo[(size_t)2 * DI * NE];
__device__ __nv_bfloat16 g_xc_hi [(size_t)MROWS * DI];
__device__ __nv_bfloat16 g_xc_lo [(size_t)MROWS * DI];
__device__ __nv_bfloat16 g_Wx_hi [(size_t)XDBL * DI];
__device__ __nv_bfloat16 g_Wx_lo [(size_t)XDBL * DI];
__device__ __nv_bfloat16 g_u_hi  [(size_t)MROWS * DI];
__device__ __nv_bfloat16 g_u_lo  [(size_t)MROWS * DI];
__device__ __nv_bfloat16 g_Wout_hi[(size_t)NE * DI];
__device__ __nv_bfloat16 g_Wout_lo[(size_t)NE * DI];

// ============================================================
// warp-level MMA helpers (sm_80+ baseline ISA, no 'a' features)
// ============================================================
__device__ __forceinline__ uint32_t smem_u32(const void* p) {
    uint32_t a;
    asm("{ .reg .u64 t; cvta.to.shared.u64 t, %1; cvt.u32.u64 %0, t; }"
        : "=r"(a) : "l"(p));
    return a;
}
__device__ __forceinline__ void ldsm_x4(uint32_t addr, uint32_t r[4]) {
    asm volatile("ldmatrix.sync.aligned.m8n8.x4.shared.b16 {%0,%1,%2,%3}, [%4];"
                 : "=r"(r[0]), "=r"(r[1]), "=r"(r[2]), "=r"(r[3]) : "r"(addr));
}
__device__ __forceinline__ void mma_bf16(float c[4], const uint32_t a[4], const uint32_t b[2]) {
    asm volatile(
        "mma.sync.aligned.m16n8k16.row.col.f32.bf16.bf16.f32 "
        "{%0,%1,%2,%3}, {%4,%5,%6,%7}, {%8,%9}, {%0,%1,%2,%3};"
        : "+f"(c[0]), "+f"(c[1]), "+f"(c[2]), "+f"(c[3])
        : "r"(a[0]), "r"(a[1]), "r"(a[2]), "r"(a[3]), "r"(b[0]), "r"(b[1]));
}

// ============================================================
// split-bf16 HMMA GEMM: C[M,N] = A[M,K] @ B[N,K]^T
// 128x128 CTA tile, BK=32, 256 threads (8 warps, 64x32 each)
// A/B given as hi+lo bf16; computes Ah*Bh + Ah*Bl + Al*Bh.
// M % 128 == 0, K % 32 == 0 assumed; N guarded.
// ============================================================
#define LDT 40   // padded row length (bf16) => 80B stride, conflict-free

__global__ __launch_bounds__(256) void gemm_mma(
    const __nv_bfloat16* __restrict__ Ah, const __nv_bfloat16* __restrict__ Al,
    const __nv_bfloat16* __restrict__ Bh, const __nv_bfloat16* __restrict__ Bl,
    float* __restrict__ C, int M, int N, int K)
{
    __shared__ __align__(16) __nv_bfloat16 sAh[128][LDT];
    __shared__ __align__(16) __nv_bfloat16 sAl[128][LDT];
    __shared__ __align__(16) __nv_bfloat16 sBh[128][LDT];
    __shared__ __align__(16) __nv_bfloat16 sBl[128][LDT];

    const int tid  = threadIdx.x;
    const int wid  = tid >> 5;
    const int lane = tid & 31;
    const int row0 = blockIdx.y * 128;
    const int col0 = blockIdx.x * 128;

    const int wm = (wid >> 2) * 64;   // warp row offset within tile (0/64)
    const int wn = (wid & 3) * 32;    // warp col offset within tile (0/32/64/96)

    float acc[4][4][4];
    #pragma unroll
    for (int i = 0; i < 4; i++)
        #pragma unroll
        for (int j = 0; j < 4; j++)
            #pragma unroll
            for (int v = 0; v < 4; v++) acc[i][j][v] = 0.f;

    // ldmatrix source addresses (fixed per lane)
    // A x4 (16x16 tile): lanes 0-15 -> row r, k 0; lanes 16-31 -> row r, k 8
    const int a_r = lane & 15, a_c = (lane >> 4) << 3;
    // B x4 (covers 16 n-rows x 16 k): matrix = lane/8:
    //   m0: n r, k0 ; m1: n r, k8 ; m2: n r+8, k0 ; m3: n r+8, k8
    const int b_mat = lane >> 3, b_r8 = lane & 7;
    const int b_r = b_r8 + ((b_mat >> 1) << 3);
    const int b_c = (b_mat & 1) << 3;

    const int groupID = lane >> 2;   // 0-7
    const int tig     = lane & 3;    // 0-3

    const int nchunks = K >> 5;
    for (int kc = 0; kc < nchunks; kc++) {
        const int k0 = kc << 5;

        // ---- load tiles: 128 rows x 32 bf16 each, 2 uint4 per row ----
        {
            int r = tid >> 1;              // 0..127
            int seg = (tid & 1) << 3;      // 0 or 8 (bf16 elems); two passes r and r+... wait 256 threads cover 128 rows x 2 segs... need 2x: each (r,seg) pair once -> 256 slots exactly for 16 elems? 32 bf16 per row = 2 uint4? No: 32 bf16 = 64B = 4 uint4.
            (void)r; (void)seg;
        }
        // 128 rows x 4 uint4-segments = 512 slots; 256 threads -> 2 each
        #pragma unroll
        for (int i = 0; i < 2; i++) {
            int s = tid + (i << 8);        // 0..511
            int r = s >> 2;                // 0..127
            int c8 = (s & 3) << 3;         // 0,8,16,24 bf16 elems
            size_t goff = (size_t)(row0 + r) * K + k0 + c8;
            *(uint4*)&sAh[r][c8] = *(const uint4*)(Ah + goff);
            *(uint4*)&sAl[r][c8] = *(const uint4*)(Al + goff);
            int gn = col0 + r;
            uint4 vh = make_uint4(0,0,0,0), vl = make_uint4(0,0,0,0);
            if (gn < N) {
                size_t boff = (size_t)gn * K + k0 + c8;
                vh = *(const uint4*)(Bh + boff);
                vl = *(const uint4*)(Bl + boff);
            }
            *(uint4*)&sBh[r][c8] = vh;
            *(uint4*)&sBl[r][c8] = vl;
        }
        __syncthreads();

        #pragma unroll
        for (int ks = 0; ks < 2; ks++) {
            const int kk = ks << 4;
            uint32_t ah[4][4], al[4][4];
            #pragma unroll
            for (int mi = 0; mi < 4; mi++) {
                uint32_t addr_h = smem_u32(&sAh[wm + mi * 16 + a_r][kk + a_c]);
                uint32_t addr_l = smem_u32(&sAl[wm + mi * 16 + a_r][kk + a_c]);
                ldsm_x4(addr_h, ah[mi]);
                ldsm_x4(addr_l, al[mi]);
            }
            uint32_t bh[4][2], bl[4][2];
            #pragma unroll
            for (int np = 0; np < 2; np++) {   // each x4 covers 16 n-cols = 2 n-tiles
                uint32_t rh[4], rl[4];
                uint32_t addr_h = smem_u32(&sBh[wn + np * 16 + b_r][kk + b_c]);
                uint32_t addr_l = smem_u32(&sBl[wn + np * 16 + b_r][kk + b_c]);
                ldsm_x4(addr_h, rh);
                ldsm_x4(addr_l, rl);
                bh[np*2][0] = rh[0]; bh[np*2][1] = rh[1];
                bh[np*2+1][0] = rh[2]; bh[np*2+1][1] = rh[3];
                bl[np*2][0] = rl[0]; bl[np*2][1] = rl[1];
                bl[np*2+1][0] = rl[2]; bl[np*2+1][1] = rl[3];
            }
            #pragma unroll
            for (int mi = 0; mi < 4; mi++)
                #pragma unroll
                for (int ni = 0; ni < 4; ni++) {
                    mma_bf16(acc[mi][ni], ah[mi], bh[ni]);
                    mma_bf16(acc[mi][ni], ah[mi], bl[ni]);
                    mma_bf16(acc[mi][ni], al[mi], bh[ni]);
                }
        }
        __syncthreads();
    }

    // ---- epilogue ----
    #pragma unroll
    for (int mi = 0; mi < 4; mi++) {
        #pragma unroll
        for (int ni = 0; ni < 4; ni++) {
            int col = col0 + wn + ni * 8 + tig * 2;
            if (col >= N) continue;
            int r0 = row0 + wm + mi * 16 + groupID;
            float2 v01 = make_float2(acc[mi][ni][0], acc[mi][ni][1]);
            float2 v23 = make_float2(acc[mi][ni][2], acc[mi][ni][3]);
            *(float2*)(C + (size_t)r0 * N + col) = v01;
            *(float2*)(C + (size_t)(r0 + 8) * N + col) = v23;
        }
    }
}

// ============================================================
// fp32 -> bf16 hi/lo split
// ============================================================
__global__ __launch_bounds__(256) void cvt_split(
    const float* __restrict__ in, __nv_bfloat16* __restrict__ hi,
    __nv_bfloat16* __restrict__ lo, int n)
{
    int idx = blockIdx.x * blockDim.x + threadIdx.x;
    if (idx >= n) return;
    float v = in[idx];
    __nv_bfloat16 h = __float2bfloat16(v);
    hi[idx] = h;
    lo[idx] = __float2bfloat16(v - __bfloat162float(h));
}

// ============================================================
// Depthwise causal conv(4) + bias + SiLU (+ bf16 split output)
// ============================================================
__global__ __launch_bounds__(256) void conv_silu_kernel(
    const float* __restrict__ conv_w, const float* __restrict__ conv_b)
{
    int idx = blockIdx.x * blockDim.x + threadIdx.x;
    if (idx >= MROWS * DI) return;
    int d = idx % DI;
    int m = idx / DI;
    int t = m % SEQ;

    float acc = conv_b[d];
    #pragma unroll
    for (int k = 0; k < 4; k++) {
        int tt = t - 3 + k;
        if (tt >= 0)
            acc = fmaf(conv_w[d * 4 + k],
                       g_xr[(size_t)(m - 3 + k) * (2 * DI) + d], acc);
    }
    float s = acc / (1.f + __expf(-acc));
    g_xc[idx] = s;
    __nv_bfloat16 h = __float2bfloat16(s);
    g_xc_hi[idx] = h;
    g_xc_lo[idx] = __float2bfloat16(s - __bfloat162float(h));
}

// ============================================================
// delta = softplus(x_dbl[:, :4] @ W_dt^T + b_dt)
// ============================================================
__global__ __launch_bounds__(256) void delta_kernel(
    const float* __restrict__ W_dt, const float* __restrict__ b_dt)
{
    int idx = blockIdx.x * blockDim.x + threadIdx.x;
    if (idx >= MROWS * DI) return;
    int d = idx % DI;
    int m = idx / DI;
    const float* xd = g_xdbl + (size_t)m * XDBL;
    float z = b_dt[d];
    #pragma unroll
    for (int r = 0; r < DTR; r++)
        z = fmaf(xd[r], W_dt[d * DTR + r], z);
    float sp = (z > 20.f) ? z : log1pf(__expf(z));
    g_delta[idx] = sp;
}

// ============================================================
// Selective scan: one warp per (b, d); each lane owns 2 states.
// Writes u = (y + D*x) * silu(res), plus bf16 split of u.
// ============================================================
__global__ __launch_bounds__(256) void scan_kernel(
    const float* __restrict__ A_log, const float* __restrict__ Dvec)
{
    const int warpId = threadIdx.x >> 5;
    const int lane   = threadIdx.x & 31;
    const int wg     = blockIdx.x * (blockDim.x >> 5) + warpId;
    if (wg >= BATCH * DI) return;
    const int b = wg / DI;
    const int d = wg % DI;
    const int n0 = 2 * lane;

    const float A0 = -__expf(A_log[d * DS + n0]);
    const float A1 = -__expf(A_log[d * DS + n0 + 1]);
    const float Dd = Dvec[d];

    const float* deltaP = g_delta + (size_t)b * SEQ * DI + d;
    const float* xP     = g_xc    + (size_t)b * SEQ * DI + d;
    const float* resP   = g_xr    + (size_t)b * SEQ * (2 * DI) + DI + d;
    const float* bcP    = g_xdbl  + (size_t)b * SEQ * XDBL;
    float*       uP     = g_u     + (size_t)b * SEQ * DI + d;
    __nv_bfloat16* uhP  = g_u_hi  + (size_t)b * SEQ * DI + d;
    __nv_bfloat16* ulP  = g_u_lo  + (size_t)b * SEQ * DI + d;

    float h0 = 0.f, h1 = 0.f;

    float  dt_n = deltaP[0];
    float  x_n  = xP[0];
    float  r_n  = resP[0];
    float2 B_n  = *(const float2*)(bcP + DTR + n0);
    float2 C_n  = *(const float2*)(bcP + DTR + DS + n0);

    for (int t = 0; t < SEQ; t++) {
        const float  dt = dt_n, xv = x_n, rv = r_n;
        const float2 Bv = B_n,  Cv = C_n;
        if (t + 1 < SEQ) {
            dt_n = deltaP[(size_t)(t + 1) * DI];
            x_n  = xP[(size_t)(t + 1) * DI];
            r_n  = resP[(size_t)(t + 1) * (2 * DI)];
            B_n  = *(const float2*)(bcP + (size_t)(t + 1) * XDBL + DTR + n0);
            C_n  = *(const float2*)(bcP + (size_t)(t + 1) * XDBL + DTR + DS + n0);
        }

        const float ab0 = __expf(dt * A0);
        const float ab1 = __expf(dt * A1);
        const float dx  = dt * xv;
        h0 = fmaf(ab0, h0, dx * Bv.x);
        h1 = fmaf(ab1, h1, dx * Bv.y);

        float p = fmaf(h0, Cv.x, h1 * Cv.y);
        #pragma unroll
        for (int o = 16; o; o >>= 1)
            p += __shfl_xor_sync(0xffffffffu, p, o);

        if (lane == 0) {
            const float y   = fmaf(Dd, xv, p);
            const float sig = 1.f / (1.f + __expf(-rv));
            const float u   = y * (rv * sig);
            uP[(size_t)t * DI] = u;
            __nv_bfloat16 h = __float2bfloat16(u);
            uhP[(size_t)t * DI] = h;
            ulP[(size_t)t * DI] = __float2bfloat16(u - __bfloat162float(h));
        }
    }
}

// ============================================================
// launch
// ============================================================
extern "C" void kernel_launch(void* const* d_in, const int* in_sizes, int n_in,
                              void* d_out, int out_size)
{
    const float* x      = (const float*)d_in[0];
    const float* W_in   = (const float*)d_in[1];
    const float* conv_w = (const float*)d_in[2];
    const float* conv_b = (const float*)d_in[3];
    const float* W_x    = (const float*)d_in[4];
    const float* W_dt   = (const float*)d_in[5];
    const float* b_dt   = (const float*)d_in[6];
    const float* A_log  = (const float*)d_in[7];
    const float* Dvec   = (const float*)d_in[8];
    const float* W_out  = (const float*)d_in[9];
    float* out = (float*)d_out;

    void *p_xr, *p_xdbl, *p_u;
    cudaGetSymbolAddress(&p_xr,   g_xr);
    cudaGetSymbolAddress(&p_xdbl, g_xdbl);
    cudaGetSymbolAddress(&p_u,    g_u);
    void *p_xhi, *p_xlo, *p_winhi, *p_winlo, *p_xchi, *p_xclo;
    void *p_wxhi, *p_wxlo, *p_uhi, *p_ulo, *p_wohi, *p_wolo;
    cudaGetSymbolAddress(&p_xhi,   g_x_hi);   cudaGetSymbolAddress(&p_xlo,   g_x_lo);
    cudaGetSymbolAddress(&p_winhi, g_Win_hi); cudaGetSymbolAddress(&p_winlo, g_Win_lo);
    cudaGetSymbolAddress(&p_xchi,  g_xc_hi);  cudaGetSymbolAddress(&p_xclo,  g_xc_lo);
    cudaGetSymbolAddress(&p_wxhi,  g_Wx_hi);  cudaGetSymbolAddress(&p_wxlo,  g_Wx_lo);
    cudaGetSymbolAddress(&p_uhi,   g_u_hi);   cudaGetSymbolAddress(&p_ulo,   g_u_lo);
    cudaGetSymbolAddress(&p_wohi,  g_Wout_hi);cudaGetSymbolAddress(&p_wolo,  g_Wout_lo);

    // 0) splits for GEMM inputs
    {
        int n = MROWS * NE;
        cvt_split<<<(n + 255) / 256, 256>>>(x, (__nv_bfloat16*)p_xhi, (__nv_bfloat16*)p_xlo, n);
        n = 2 * DI * NE;
        cvt_split<<<(n + 255) / 256, 256>>>(W_in, (__nv_bfloat16*)p_winhi, (__nv_bfloat16*)p_winlo, n);
        n = XDBL * DI;
        cvt_split<<<(n + 255) / 256, 256>>>(W_x, (__nv_bfloat16*)p_wxhi, (__nv_bfloat16*)p_wxlo, n);
        n = NE * DI;
        cvt_split<<<(n + 255) / 256, 256>>>(W_out, (__nv_bfloat16*)p_wohi, (__nv_bfloat16*)p_wolo, n);
    }
    // 1) xr = x @ W_in^T : [4096, 3072], K=768
    {
        dim3 grid((2 * DI + 127) / 128, MROWS / 128);
        gemm_mma<<<grid, 256>>>(
            (const __nv_bfloat16*)p_xhi, (const __nv_bfloat16*)p_xlo,
            (const __nv_bfloat16*)p_winhi, (const __nv_bfloat16*)p_winlo,
            (float*)p_xr, MROWS, 2 * DI, NE);
    }
    // 2) conv + silu (+ split)
    {
        int n = MROWS * DI;
        conv_silu_kernel<<<(n + 255) / 256, 256>>>(conv_w, conv_b);
    }
    // 3) x_dbl = x_ssm @ W_x^T : [4096, 132], K=1536
    {
        dim3 grid((XDBL + 127) / 128, MROWS / 128);
        gemm_mma<<<grid, 256>>>(
            (const __nv_bfloat16*)p_xchi, (const __nv_bfloat16*)p_xclo,
            (const __nv_bfloat16*)p_wxhi, (const __nv_bfloat16*)p_wxlo,
            (float*)p_xdbl, MROWS, XDBL, DI);
    }
    // 4) delta
    {
        int n = MROWS * DI;
        delta_kernel<<<(n + 255) / 256, 256>>>(W_dt, b_dt);
    }
    // 5) selective scan -> u (+ split inside)
    {
        int nwarps = BATCH * DI;
        int wpb = 8;
        scan_kernel<<<(nwarps + wpb - 1) / wpb, wpb * 32>>>(A_log, Dvec);
    }
    // 6) out = u @ W_out^T : [4096, 768], K=1536
    {
        dim3 grid(NE / 128, MROWS / 128);
        gemm_mma<<<grid, 256>>>(
            (const __nv_bfloat16*)p_uhi, (const __nv_bfloat16*)p_ulo,
            (const __nv_bfloat16*)p_wohi, (const __nv_bfloat16*)p_wolo,
            out, MROWS, NE, DI);
    }
}

// round 6
// speedup vs baseline: 1.7639x; 1.4596x over previous
#include <cuda_runtime.h>
#include <cuda_fp16.h>
#include <cstdint>
#include <math.h>

// ---- problem constants ----
#define BATCH 4
#define SEQ   1024
#define NE    768
#define DI    1536          // d_inner
#define DS    64            // d_state
#define DTR   4             // dt_rank
#define XDBL  (DTR + 2*DS)  // 132
#define MROWS (BATCH*SEQ)   // 4096

// ---- fp32 scratch ----
__device__ float g_xr   [(size_t)MROWS * 2 * DI];
__device__ float g_xc   [(size_t)MROWS * DI];
__device__ float g_xdbl [(size_t)MROWS * XDBL];
__device__ float g_delta[(size_t)MROWS * DI];

// ---- fp16 GEMM operands ----
__device__ __half g_x_h   [(size_t)MROWS * NE];
__device__ __half g_Win_h [(size_t)2 * DI * NE];
__device__ __half g_xc_h  [(size_t)MROWS * DI];
__device__ __half g_Wx_h  [(size_t)XDBL * DI];
__device__ __half g_u_h   [(size_t)MROWS * DI];
__device__ __half g_Wout_h[(size_t)NE * DI];

// ============================================================
// warp-MMA + cp.async helpers (baseline sm_80+ ISA)
// ============================================================
__device__ __forceinline__ uint32_t smem_u32(const void* p) {
    uint32_t a;
    asm("{ .reg .u64 t; cvta.to.shared.u64 t, %1; cvt.u32.u64 %0, t; }"
        : "=r"(a) : "l"(p));
    return a;
}
__device__ __forceinline__ void ldsm_x4(uint32_t addr, uint32_t r[4]) {
    asm volatile("ldmatrix.sync.aligned.m8n8.x4.shared.b16 {%0,%1,%2,%3}, [%4];"
                 : "=r"(r[0]), "=r"(r[1]), "=r"(r[2]), "=r"(r[3]) : "r"(addr));
}
__device__ __forceinline__ void mma_f16(float c[4], const uint32_t a[4], const uint32_t b[2]) {
    asm volatile(
        "mma.sync.aligned.m16n8k16.row.col.f32.f16.f16.f32 "
        "{%0,%1,%2,%3}, {%4,%5,%6,%7}, {%8,%9}, {%0,%1,%2,%3};"
        : "+f"(c[0]), "+f"(c[1]), "+f"(c[2]), "+f"(c[3])
        : "r"(a[0]), "r"(a[1]), "r"(a[2]), "r"(a[3]), "r"(b[0]), "r"(b[1]));
}
__device__ __forceinline__ void cp16(uint32_t dst, const void* src, uint32_t srcsz) {
    asm volatile("cp.async.cg.shared.global [%0], [%1], 16, %2;"
                 :: "r"(dst), "l"(src), "r"(srcsz));
}
#define CP_COMMIT() asm volatile("cp.async.commit_group;")
#define CP_WAIT1()  asm volatile("cp.async.wait_group 1;")

// ============================================================
// fp16 pipelined HMMA GEMM: C[M,N] = A[M,K] @ B[N,K]^T
// 128x128 CTA tile, BK=32, 3-stage cp.async pipeline,
// 256 threads (8 warps, each 64x32 of C).
// M%128==0, K%32==0 assumed; N guarded.
// ============================================================
#define LDT      40                          // padded row (halves) -> 80B stride (16B-mult!)
#define STAGE_A  (128 * LDT * 2)             // 10240 B
#define STAGE_SZ (2 * STAGE_A)               // A + B per stage = 20480 B
#define NSTAGE   3
#define G_SMEM   (NSTAGE * STAGE_SZ)         // 61440 B

__global__ __launch_bounds__(256, 2) void gemm_h(
    const __half* __restrict__ A, const __half* __restrict__ B,
    float* __restrict__ C, int M, int N, int K)
{
    extern __shared__ __align__(16) char dsm[];
    const uint32_t sb = smem_u32(dsm);

    const int tid  = threadIdx.x;
    const int wid  = tid >> 5;
    const int lane = tid & 31;
    const int row0 = blockIdx.y * 128;
    const int col0 = blockIdx.x * 128;
    const int wm   = (wid >> 2) * 64;
    const int wn   = (wid & 3) * 32;

    float acc[4][4][4];
    #pragma unroll
    for (int i = 0; i < 4; i++)
        #pragma unroll
        for (int j = 0; j < 4; j++)
            #pragma unroll
            for (int v = 0; v < 4; v++) acc[i][j][v] = 0.f;

    // ldmatrix lane addressing
    const int a_r = lane & 15, a_c = (lane >> 4) << 3;
    const int b_mat = lane >> 3;
    const int b_r = (lane & 7) + ((b_mat >> 1) << 3);
    const int b_c = (b_mat & 1) << 3;

    // per-thread load slots
    const int l_r  = tid >> 2;           // rows 0..63 (+64 on second pass)
    const int l_c8 = (tid & 3) << 3;     // 0,8,16,24

    auto issue = [&](int kc, int st) {
        const int k0 = kc << 5;
        const uint32_t aBase = sb + st * STAGE_SZ;
        const uint32_t bBase = aBase + STAGE_A;
        #pragma unroll
        for (int i = 0; i < 2; i++) {
            const int r = l_r + (i << 6);         // 0..127
            const uint32_t so = (uint32_t)(r * LDT + l_c8) * 2;   // r*80 + l_c8*2, 16B-mult
            cp16(aBase + so, A + (size_t)(row0 + r) * K + k0 + l_c8, 16);
            const int gn = col0 + r;
            const int gcl = gn < N ? gn : (N - 1);
            cp16(bBase + so, B + (size_t)gcl * K + k0 + l_c8, gn < N ? 16u : 0u);
        }
        CP_COMMIT();
    };

    const int nch = K >> 5;
    issue(0, 0);
    issue(1, 1);

    for (int kc = 0; kc < nch; kc++) {
        const int st = kc % NSTAGE;
        CP_WAIT1();
        __syncthreads();
        if (kc + 2 < nch) issue(kc + 2, (kc + 2) % NSTAGE);
        else CP_COMMIT();

        const uint32_t aBase = sb + st * STAGE_SZ;
        const uint32_t bBase = aBase + STAGE_A;

        #pragma unroll
        for (int ks = 0; ks < 2; ks++) {
            const int kk = ks << 4;
            uint32_t af[4][4];
            #pragma unroll
            for (int mi = 0; mi < 4; mi++)
                ldsm_x4(aBase + (uint32_t)((wm + mi * 16 + a_r) * LDT + kk + a_c) * 2, af[mi]);
            uint32_t bf[4][2];
            #pragma unroll
            for (int np = 0; np < 2; np++) {
                uint32_t r4[4];
                ldsm_x4(bBase + (uint32_t)((wn + np * 16 + b_r) * LDT + kk + b_c) * 2, r4);
                bf[np * 2][0] = r4[0]; bf[np * 2][1] = r4[1];
                bf[np * 2 + 1][0] = r4[2]; bf[np * 2 + 1][1] = r4[3];
            }
            #pragma unroll
            for (int mi = 0; mi < 4; mi++)
                #pragma unroll
                for (int ni = 0; ni < 4; ni++)
                    mma_f16(acc[mi][ni], af[mi], bf[ni]);
        }
        __syncthreads();
    }

    // ---- epilogue ----
    const int groupID = lane >> 2, tig = lane & 3;
    #pragma unroll
    for (int mi = 0; mi < 4; mi++) {
        #pragma unroll
        for (int ni = 0; ni < 4; ni++) {
            int col = col0 + wn + ni * 8 + tig * 2;
            if (col >= N) continue;
            int r0 = row0 + wm + mi * 16 + groupID;
            *(float2*)(C + (size_t)r0 * N + col) =
                make_float2(acc[mi][ni][0], acc[mi][ni][1]);
            *(float2*)(C + (size_t)(r0 + 8) * N + col) =
                make_float2(acc[mi][ni][2], acc[mi][ni][3]);
        }
    }
}

// ============================================================
// fp32 -> fp16 convert
// ============================================================
__global__ __launch_bounds__(256) void cvt_half(
    const float* __restrict__ in, __half* __restrict__ out, int n)
{
    int idx = blockIdx.x * blockDim.x + threadIdx.x;
    if (idx < n) out[idx] = __float2half(in[idx]);
}

// ============================================================
// Depthwise causal conv(4) + bias + SiLU (fp32 + fp16 outs)
// ============================================================
__global__ __launch_bounds__(256) void conv_silu_kernel(
    const float* __restrict__ conv_w, const float* __restrict__ conv_b)
{
    int idx = blockIdx.x * blockDim.x + threadIdx.x;
    if (idx >= MROWS * DI) return;
    int d = idx % DI;
    int m = idx / DI;
    int t = m % SEQ;

    float acc = conv_b[d];
    #pragma unroll
    for (int k = 0; k < 4; k++) {
        int tt = t - 3 + k;
        if (tt >= 0)
            acc = fmaf(conv_w[d * 4 + k],
                       g_xr[(size_t)(m - 3 + k) * (2 * DI) + d], acc);
    }
    float s = acc / (1.f + __expf(-acc));
    g_xc[idx]   = s;
    g_xc_h[idx] = __float2half(s);
}

// ============================================================
// delta = softplus(x_dbl[:, :4] @ W_dt^T + b_dt)
// ============================================================
__global__ __launch_bounds__(256) void delta_kernel(
    const float* __restrict__ W_dt, const float* __restrict__ b_dt)
{
    int idx = blockIdx.x * blockDim.x + threadIdx.x;
    if (idx >= MROWS * DI) return;
    int d = idx % DI;
    int m = idx / DI;
    const float* xd = g_xdbl + (size_t)m * XDBL;
    float z = b_dt[d];
    #pragma unroll
    for (int r = 0; r < DTR; r++)
        z = fmaf(xd[r], W_dt[d * DTR + r], z);
    float sp = (z > 20.f) ? z : log1pf(__expf(z));
    g_delta[idx] = sp;
}

// ============================================================
// Selective scan: one warp per (b, d); each lane owns 2 states.
// Writes u_h = fp16((y + D*x) * silu(res))
// ============================================================
__global__ __launch_bounds__(256) void scan_kernel(
    const float* __restrict__ A_log, const float* __restrict__ Dvec)
{
    const int warpId = threadIdx.x >> 5;
    const int lane   = threadIdx.x & 31;
    const int wg     = blockIdx.x * (blockDim.x >> 5) + warpId;
    if (wg >= BATCH * DI) return;
    const int b = wg / DI;
    const int d = wg % DI;
    const int n0 = 2 * lane;

    const float A0 = -__expf(A_log[d * DS + n0]);
    const float A1 = -__expf(A_log[d * DS + n0 + 1]);
    const float Dd = Dvec[d];

    const float* deltaP = g_delta + (size_t)b * SEQ * DI + d;
    const float* xP     = g_xc    + (size_t)b * SEQ * DI + d;
    const float* resP   = g_xr    + (size_t)b * SEQ * (2 * DI) + DI + d;
    const float* bcP    = g_xdbl  + (size_t)b * SEQ * XDBL;
    __half*      uhP    = g_u_h   + (size_t)b * SEQ * DI + d;

    float h0 = 0.f, h1 = 0.f;

    float  dt_n = deltaP[0];
    float  x_n  = xP[0];
    float  r_n  = resP[0];
    float2 B_n  = *(const float2*)(bcP + DTR + n0);
    float2 C_n  = *(const float2*)(bcP + DTR + DS + n0);

    for (int t = 0; t < SEQ; t++) {
        const float  dt = dt_n, xv = x_n, rv = r_n;
        const float2 Bv = B_n,  Cv = C_n;
        if (t + 1 < SEQ) {
            dt_n = deltaP[(size_t)(t + 1) * DI];
            x_n  = xP[(size_t)(t + 1) * DI];
            r_n  = resP[(size_t)(t + 1) * (2 * DI)];
            B_n  = *(const float2*)(bcP + (size_t)(t + 1) * XDBL + DTR + n0);
            C_n  = *(const float2*)(bcP + (size_t)(t + 1) * XDBL + DTR + DS + n0);
        }

        const float ab0 = __expf(dt * A0);
        const float ab1 = __expf(dt * A1);
        const float dx  = dt * xv;
        h0 = fmaf(ab0, h0, dx * Bv.x);
        h1 = fmaf(ab1, h1, dx * Bv.y);

        float p = fmaf(h0, Cv.x, h1 * Cv.y);
        #pragma unroll
        for (int o = 16; o; o >>= 1)
            p += __shfl_xor_sync(0xffffffffu, p, o);

        if (lane == 0) {
            const float y   = fmaf(Dd, xv, p);
            const float sig = 1.f / (1.f + __expf(-rv));
            uhP[(size_t)t * DI] = __float2half(y * (rv * sig));
        }
    }
}

// ============================================================
// launch
// ============================================================
extern "C" void kernel_launch(void* const* d_in, const int* in_sizes, int n_in,
                              void* d_out, int out_size)
{
    const float* x      = (const float*)d_in[0];
    const float* W_in   = (const float*)d_in[1];
    const float* conv_w = (const float*)d_in[2];
    const float* conv_b = (const float*)d_in[3];
    const float* W_x    = (const float*)d_in[4];
    const float* W_dt   = (const float*)d_in[5];
    const float* b_dt   = (const float*)d_in[6];
    const float* A_log  = (const float*)d_in[7];
    const float* Dvec   = (const float*)d_in[8];
    const float* W_out  = (const float*)d_in[9];
    float* out = (float*)d_out;

    static bool attr_done = false;
    if (!attr_done) {
        cudaFuncSetAttribute(gemm_h, cudaFuncAttributeMaxDynamicSharedMemorySize, G_SMEM);
        attr_done = true;
    }

    void *p_xr, *p_xdbl;
    cudaGetSymbolAddress(&p_xr,   g_xr);
    cudaGetSymbolAddress(&p_xdbl, g_xdbl);
    void *p_xh, *p_winh, *p_xch, *p_wxh, *p_uh, *p_woh;
    cudaGetSymbolAddress(&p_xh,   g_x_h);
    cudaGetSymbolAddress(&p_winh, g_Win_h);
    cudaGetSymbolAddress(&p_xch,  g_xc_h);
    cudaGetSymbolAddress(&p_wxh,  g_Wx_h);
    cudaGetSymbolAddress(&p_uh,   g_u_h);
    cudaGetSymbolAddress(&p_woh,  g_Wout_h);

    // 0) fp16 converts
    {
        int n = MROWS * NE;
        cvt_half<<<(n + 255) / 256, 256>>>(x, (__half*)p_xh, n);
        n = 2 * DI * NE;
        cvt_half<<<(n + 255) / 256, 256>>>(W_in, (__half*)p_winh, n);
        n = XDBL * DI;
        cvt_half<<<(n + 255) / 256, 256>>>(W_x, (__half*)p_wxh, n);
        n = NE * DI;
        cvt_half<<<(n + 255) / 256, 256>>>(W_out, (__half*)p_woh, n);
    }
    // 1) xr = x @ W_in^T : [4096, 3072], K=768
    {
        dim3 grid((2 * DI) / 128, MROWS / 128);
        gemm_h<<<grid, 256, G_SMEM>>>((const __half*)p_xh, (const __half*)p_winh,
                                      (float*)p_xr, MROWS, 2 * DI, NE);
    }
    // 2) conv + silu
    {
        int n = MROWS * DI;
        conv_silu_kernel<<<(n + 255) / 256, 256>>>(conv_w, conv_b);
    }
    // 3) x_dbl = x_ssm @ W_x^T : [4096, 132], K=1536
    {
        dim3 grid((XDBL + 127) / 128, MROWS / 128);
        gemm_h<<<grid, 256, G_SMEM>>>((const __half*)p_xch, (const __half*)p_wxh,
                                      (float*)p_xdbl, MROWS, XDBL, DI);
    }
    // 4) delta
    {
        int n = MROWS * DI;
        delta_kernel<<<(n + 255) / 256, 256>>>(W_dt, b_dt);
    }
    // 5) selective scan -> u_h
    {
        int nwarps = BATCH * DI;
        int wpb = 8;
        scan_kernel<<<(nwarps + wpb - 1) / wpb, wpb * 32>>>(A_log, Dvec);
    }
    // 6) out = u @ W_out^T : [4096, 768], K=1536
    {
        dim3 grid(NE / 128, MROWS / 128);
        gemm_h<<<grid, 256, G_SMEM>>>((const __half*)p_uh, (const __half*)p_woh,
                                      out, MROWS, NE, DI);
    }
}